// round 8
// baseline (speedup 1.0000x reference)
#include <cuda_runtime.h>
#include <cuda_fp16.h>
#include <math.h>

#define N 8192
#define M 8192
#define D 64
#define NIT 20

typedef unsigned long long ull;
typedef unsigned int uint;

static constexpr float EPS   = 0.05f;
static constexpr float ALPHA = 1.4426950408889634f;   // log2(e)
static constexpr float LN2   = 0.6931471805599453f;
static constexpr float KC    = (2.0f / 0.05f) * 1.4426950408889634f; // 57.7

// ---------------- scratch (device globals) ----------------
__device__ unsigned char  dA8 [N * M];   // round(KC*dot/32)+128
__device__ unsigned char  dAT8[N * M];   // transpose
__device__ float  d_vt[N];               // potentials (log2/t units)
__device__ float  d_wt[M];
__device__ __half d_vtp[N];              // v/32 - 1152 (phase-1 operand)
__device__ __half d_wtp[M];
__device__ float  d_la[N];
__device__ float  d_lb[M];
__device__ float  d_x2[N];
__device__ float  d_y2[M];
__device__ float  d_an[N];
__device__ float  d_bn[M];
__device__ float  d_sums[2];

// ---------------- helpers ----------------
__device__ __forceinline__ float ex2(float x) {
    float r; asm("ex2.approx.f32 %0, %1;" : "=f"(r) : "f"(x)); return r;
}
__device__ __forceinline__ __half2 h2bits(uint u) {
    __half2 h; asm("mov.b32 %0, %1;" : "=r"(*(uint*)&h) : "r"(u)); return h;
}
__device__ __forceinline__ void fma2(ull& d, ull a, ull b) {
    asm("fma.rn.f32x2 %0, %1, %2, %0;" : "+l"(d) : "l"(a), "l"(b));
}
__device__ __forceinline__ ull bcast2(float a) {
    ull p; asm("mov.b64 %0, {%1, %1};" : "=l"(p) : "f"(a)); return p;
}
__device__ __forceinline__ void unpack2(ull p, float& lo, float& hi) {
    asm("mov.b64 {%0, %1}, %2;" : "=f"(lo), "=f"(hi) : "l"(p));
}
__device__ __forceinline__ ull pack2(float lo, float hi) {
    ull p; asm("mov.b64 %0, {%1, %2};" : "=l"(p) : "f"(lo), "f"(hi)); return p;
}
__device__ __forceinline__ uint qbyte(float v) {       // round(v/32)+128, clamped
    float f = fminf(fmaxf(v * 0.03125f, -127.f), 127.f);
    return (uint)(__float2int_rn(f) + 128);
}

// ---------------- row squared norms ----------------
__global__ void k_sqnorm(const float* __restrict__ X, const float* __restrict__ Y) {
    int w    = (blockIdx.x * blockDim.x + threadIdx.x) >> 5;
    int lane = threadIdx.x & 31;
    if (w >= N + M) return;
    const float* src = (w < N) ? (X + (size_t)w * D) : (Y + (size_t)(w - N) * D);
    float v0 = src[lane], v1 = src[lane + 32];
    float s = v0 * v0 + v1 * v1;
    #pragma unroll
    for (int off = 16; off; off >>= 1) s += __shfl_xor_sync(0xffffffffu, s, off);
    if (lane == 0) { if (w < N) d_x2[w] = s; else d_y2[w - N] = s; }
}

// ---------------- sums ----------------
__global__ void k_sum(const float* __restrict__ a, const float* __restrict__ b) {
    __shared__ float sa[1024], sb[1024];
    int t = threadIdx.x;
    float s1 = 0.f, s2 = 0.f;
    for (int i = t; i < N; i += 1024) s1 += a[i];
    for (int j = t; j < M; j += 1024) s2 += b[j];
    sa[t] = s1; sb[t] = s2; __syncthreads();
    for (int off = 512; off; off >>= 1) {
        if (t < off) { sa[t] += sa[t + off]; sb[t] += sb[t + off]; }
        __syncthreads();
    }
    if (t == 0) { d_sums[0] = sa[0]; d_sums[1] = sb[0]; }
}

// ---------------- init ----------------
__global__ void k_init(const float* __restrict__ a, const float* __restrict__ b) {
    int i = blockIdx.x * blockDim.x + threadIdx.x;
    if (i >= N) return;
    float lsa = logf(d_sums[0]), lsb = logf(d_sums[1]);
    float ai = a[i];
    d_la[i] = ALPHA * (logf(ai) - lsa);
    d_an[i] = ai / d_sums[0];
    float bi = b[i];
    float lb = ALPHA * (logf(bi) - lsb);
    d_lb[i] = lb;
    d_bn[i] = bi / d_sums[1];
    float w0 = lb - (ALPHA / EPS) * d_y2[i];
    d_wt[i]  = w0;
    d_wtp[i] = __float2half_rn(w0 * 0.03125f - 1152.f);
}

// ---------------- GEMM: 128x128 tile, 8x8/thread, emit A8 + AT8 only -------
__global__ void __launch_bounds__(256) gemm_kernel(const float* __restrict__ X,
                                                   const float* __restrict__ Y) {
    __shared__ __align__(16) char sbuf[33792];
    float* sxT = (float*)sbuf;                 // [32][132]
    float* syT = sxT + 32 * 132;               // [32][132]
    unsigned char* ts = (unsigned char*)sbuf;  // [128][144] bytes

    int t  = threadIdx.x;
    int tx = t & 15, ty = t >> 4;
    int i0 = blockIdx.y * 128;
    int j0 = blockIdx.x * 128;

    ull acc[8][4];
    #pragma unroll
    for (int u = 0; u < 8; u++)
        #pragma unroll
        for (int v = 0; v < 4; v++) acc[u][v] = 0ull;

    #pragma unroll
    for (int k0 = 0; k0 < 64; k0 += 32) {
        if (k0) __syncthreads();
        #pragma unroll
        for (int it = 0; it < 4; it++) {
            int q = t + 256 * it;
            int r = q >> 3, c = q & 7;
            float4 fx = *reinterpret_cast<const float4*>(X + (size_t)(i0 + r) * D + k0 + c * 4);
            sxT[(c * 4 + 0) * 132 + r] = fx.x;
            sxT[(c * 4 + 1) * 132 + r] = fx.y;
            sxT[(c * 4 + 2) * 132 + r] = fx.z;
            sxT[(c * 4 + 3) * 132 + r] = fx.w;
            float4 fy = *reinterpret_cast<const float4*>(Y + (size_t)(j0 + r) * D + k0 + c * 4);
            syT[(c * 4 + 0) * 132 + r] = fy.x;
            syT[(c * 4 + 1) * 132 + r] = fy.y;
            syT[(c * 4 + 2) * 132 + r] = fy.z;
            syT[(c * 4 + 3) * 132 + r] = fy.w;
        }
        __syncthreads();

        #pragma unroll 8
        for (int k = 0; k < 32; k++) {
            float4 a0 = *reinterpret_cast<const float4*>(&sxT[k * 132 + ty * 8]);
            float4 a1 = *reinterpret_cast<const float4*>(&sxT[k * 132 + ty * 8 + 4]);
            float4 b0 = *reinterpret_cast<const float4*>(&syT[k * 132 + tx * 8]);
            float4 b1 = *reinterpret_cast<const float4*>(&syT[k * 132 + tx * 8 + 4]);
            ull bb0 = pack2(b0.x, b0.y), bb1 = pack2(b0.z, b0.w);
            ull bb2 = pack2(b1.x, b1.y), bb3 = pack2(b1.z, b1.w);
            float av[8] = {a0.x, a0.y, a0.z, a0.w, a1.x, a1.y, a1.z, a1.w};
            #pragma unroll
            for (int u = 0; u < 8; u++) {
                ull au = bcast2(av[u]);
                fma2(acc[u][0], au, bb0);
                fma2(acc[u][1], au, bb1);
                fma2(acc[u][2], au, bb2);
                fma2(acc[u][3], au, bb3);
            }
        }
    }

    __syncthreads();   // smem reads done; sbuf becomes ts

    #pragma unroll
    for (int u = 0; u < 8; u++) {
        float v[8];
        #pragma unroll
        for (int p = 0; p < 4; p++) {
            float lo, hi; unpack2(acc[u][p], lo, hi);
            v[2 * p] = lo * KC; v[2 * p + 1] = hi * KC;
        }
        uint qb[8];
        #pragma unroll
        for (int e = 0; e < 8; e++) qb[e] = qbyte(v[e]);
        uint2 pb;
        pb.x = qb[0] | (qb[1] << 8) | (qb[2] << 16) | (qb[3] << 24);
        pb.y = qb[4] | (qb[5] << 8) | (qb[6] << 16) | (qb[7] << 24);
        *reinterpret_cast<uint2*>(dA8 + (size_t)(i0 + ty * 8 + u) * M + j0 + tx * 8) = pb;
        #pragma unroll
        for (int e = 0; e < 8; e++)
            ts[(tx * 8 + e) * 144 + ty * 8 + u] = (unsigned char)qb[e];
    }

    __syncthreads();
    #pragma unroll
    for (int it = 0; it < 4; it++) {
        int q  = t + 256 * it;
        int jj = q >> 3, c = q & 7;
        uint4 o = *reinterpret_cast<const uint4*>(&ts[jj * 144 + c * 16]);
        *reinterpret_cast<uint4*>(dAT8 + (size_t)(j0 + jj) * N + i0 + c * 16) = o;
    }
}

// ---------------- two-phase LSE pass: warp/row ----------------
// Phase 1: int8 stream + fp16 w' in smem; t/32 est = HADD2(1024+b, w'); HMAX2.
// Phase 2: hot lane-groups re-scan from L2; elements with est >= thr get an
//          EXACT fp32 recompute: t = KC*dot(P[row],Q[e]) + w32[e].
// P = row-side points, Q = column-side points.
template <bool ROWPASS>
__global__ void __launch_bounds__(256) pass_kernel(const float* __restrict__ P,
                                                   const float* __restrict__ Q) {
    __shared__ __align__(16) __half swp[8192];   // 16 KB
    const unsigned char* __restrict__ Mat8 = ROWPASS ? dA8  : dAT8;
    const __half* __restrict__ wpr  = ROWPASS ? d_wtp : d_vtp;
    const float*  __restrict__ w32  = ROWPASS ? d_wt  : d_vt;
    const float*  __restrict__ lvec = ROWPASS ? d_la  : d_lb;
    float*  __restrict__ vout  = ROWPASS ? d_vt  : d_wt;
    __half* __restrict__ voutp = ROWPASS ? d_vtp : d_wtp;

    int t = threadIdx.x;
    {   // fill w' smem: 8192 halves = 1024 uint4
        const uint4* src = reinterpret_cast<const uint4*>(wpr);
        uint4* dst = reinterpret_cast<uint4*>(swp);
        #pragma unroll
        for (int it = 0; it < 4; it++) dst[t + 256 * it] = src[t + 256 * it];
    }
    __syncthreads();

    int warp = t >> 5, lane = t & 31;
    int row  = blockIdx.x * 8 + warp;
    const uint4* rp  = reinterpret_cast<const uint4*>(Mat8 + (size_t)row * M);
    const uint4* sw4 = reinterpret_cast<const uint4*>(swp);

    __half2 gmax[4];
    #pragma unroll
    for (int g = 0; g < 4; g++) gmax[g] = __floats2half2_rn(-2000.f, -2000.f);

    // ---- phase 1: depth-2 pipeline over 16 chunks (16B per lane each) ----
    uint4 cur = __ldg(&rp[lane]);
    #pragma unroll
    for (int c = 0; c < 16; c++) {
        uint4 nxt = cur;
        if (c < 15) nxt = __ldg(&rp[(c + 1) * 32 + lane]);
        int wi = (c * 32 + lane) * 2;
        uint4 wa = sw4[wi], wb = sw4[wi + 1];
        const __half2* ha = (const __half2*)&wa;
        const __half2* hb = (const __half2*)&wb;
        __half2 mx = gmax[c >> 2];
        mx = __hmax2(mx, __hmax2(
            __hadd2(h2bits(__byte_perm(cur.x, 0x00640064u, 0x4140)), ha[0]),
            __hadd2(h2bits(__byte_perm(cur.x, 0x00640064u, 0x4342)), ha[1])));
        mx = __hmax2(mx, __hmax2(
            __hadd2(h2bits(__byte_perm(cur.y, 0x00640064u, 0x4140)), ha[2]),
            __hadd2(h2bits(__byte_perm(cur.y, 0x00640064u, 0x4342)), ha[3])));
        mx = __hmax2(mx, __hmax2(
            __hadd2(h2bits(__byte_perm(cur.z, 0x00640064u, 0x4140)), hb[0]),
            __hadd2(h2bits(__byte_perm(cur.z, 0x00640064u, 0x4342)), hb[1])));
        mx = __hmax2(mx, __hmax2(
            __hadd2(h2bits(__byte_perm(cur.w, 0x00640064u, 0x4140)), hb[2]),
            __hadd2(h2bits(__byte_perm(cur.w, 0x00640064u, 0x4342)), hb[3])));
        gmax[c >> 2] = mx;
        cur = nxt;
    }

    // warp-wide approximate row max (t/32 units)
    __half2 gAll = __hmax2(__hmax2(gmax[0], gmax[1]), __hmax2(gmax[2], gmax[3]));
    float rm = fmaxf(__low2float(gAll), __high2float(gAll));
    #pragma unroll
    for (int off = 16; off; off >>= 1)
        rm = fmaxf(rm, __shfl_xor_sync(0xffffffffu, rm, off));

    float thr = rm - 4.5f;          // safe skip margin (est error <= ~1.2)
    float m2  = 32.f * rm + 50.f;   // guaranteed >= true max (t units)

    const float* prow = P + (size_t)row * D;

    // ---- phase 2: exact fp32 fix-up over hot elements ----
    float s = 0.f;
    #pragma unroll
    for (int g = 0; g < 4; g++) {
        float gf = fmaxf(__low2float(gmax[g]), __high2float(gmax[g]));
        bool hot = gf >= thr;
        if (__ballot_sync(0xffffffffu, hot)) {
            if (hot) {
                #pragma unroll
                for (int k = 0; k < 4; k++) {
                    int cc = g * 4 + k;
                    uint4 pk = __ldg(&rp[cc * 32 + lane]);   // L2 hit
                    int wi = (cc * 32 + lane) * 2;
                    uint4 wa = sw4[wi], wb = sw4[wi + 1];
                    const __half2* ha = (const __half2*)&wa;
                    const __half2* hb = (const __half2*)&wb;
                    int eb = (cc * 32 + lane) * 16;
                    uint words[4] = {pk.x, pk.y, pk.z, pk.w};
                    #pragma unroll
                    for (int q = 0; q < 4; q++) {
                        __half2 w2a = (q < 2) ? ha[2 * q]     : hb[2 * (q - 2)];
                        __half2 w2b = (q < 2) ? ha[2 * q + 1] : hb[2 * (q - 2) + 1];
                        __half2 ta = __hadd2(h2bits(__byte_perm(words[q], 0x00640064u, 0x4140)), w2a);
                        __half2 tb = __hadd2(h2bits(__byte_perm(words[q], 0x00640064u, 0x4342)), w2b);
                        float es[4] = {__low2float(ta), __high2float(ta),
                                       __low2float(tb), __high2float(tb)};
                        #pragma unroll
                        for (int z = 0; z < 4; z++) {
                            if (es[z] >= thr) {
                                int e = eb + q * 4 + z;
                                const float* qv = Q + (size_t)e * D;
                                float dot = 0.f;
                                #pragma unroll
                                for (int kk = 0; kk < 16; kk++) {
                                    float4 av = __ldg((const float4*)(prow + kk * 4));
                                    float4 bv = __ldg((const float4*)(qv + kk * 4));
                                    dot += av.x * bv.x + av.y * bv.y
                                         + av.z * bv.z + av.w * bv.w;
                                }
                                float tv = fmaf(KC, dot, __ldg(&w32[e]));
                                s += ex2(tv - m2);
                            }
                        }
                    }
                }
            }
        }
    }
    #pragma unroll
    for (int off = 16; off; off >>= 1)
        s += __shfl_xor_sync(0xffffffffu, s, off);
    if (lane == 0) {
        float r = lvec[row] - (m2 + log2f(s));
        vout[row]  = r;
        voutp[row] = __float2half_rn(r * 0.03125f - 1152.f);
    }
}

// ---------------- final reduction ----------------
__global__ void k_final(float* __restrict__ out) {
    __shared__ float sm[1024];
    int t = threadIdx.x;
    float s = 0.f;
    for (int i = t; i < N; i += 1024)
        s += d_an[i] * (d_x2[i] + EPS * LN2 * (d_vt[i] - d_la[i]));
    for (int j = t; j < M; j += 1024)
        s += d_bn[j] * (d_y2[j] + EPS * LN2 * (d_wt[j] - d_lb[j]));
    sm[t] = s; __syncthreads();
    for (int off = 512; off; off >>= 1) {
        if (t < off) sm[t] += sm[t + off];
        __syncthreads();
    }
    if (t == 0) out[0] = sm[0];
}

// ---------------- launch ----------------
extern "C" void kernel_launch(void* const* d_in, const int* in_sizes, int n_in,
                              void* d_out, int out_size) {
    const float* a = (const float*)d_in[0];
    const float* x = (const float*)d_in[1];
    const float* b = (const float*)d_in[2];
    const float* y = (const float*)d_in[3];
    float* out = (float*)d_out;

    k_sqnorm<<<(N + M) / 8, 256>>>(x, y);
    k_sum<<<1, 1024>>>(a, b);
    k_init<<<N / 256, 256>>>(a, b);
    gemm_kernel<<<dim3(M / 128, N / 128), 256>>>(x, y);

    for (int it = 0; it < NIT; ++it) {
        pass_kernel<true ><<<N / 8, 256>>>(x, y);  // v from w (A8 rows)
        pass_kernel<false><<<M / 8, 256>>>(y, x);  // w from v (AT8 rows)
    }
    pass_kernel<true><<<N / 8, 256>>>(x, y);       // f_fin; g_fin == g_20
    k_final<<<1, 1024>>>(out);
}

// round 9
// speedup vs baseline: 15.9472x; 15.9472x over previous
#include <cuda_runtime.h>
#include <cuda_fp16.h>
#include <math.h>

#define N 8192
#define M 8192
#define D 64
#define NIT 20

typedef unsigned long long ull;
typedef unsigned int uint;

static constexpr float EPS   = 0.05f;
static constexpr float ALPHA = 1.4426950408889634f;   // log2(e)
static constexpr float LN2   = 0.6931471805599453f;
static constexpr float KC    = (2.0f / 0.05f) * 1.4426950408889634f; // 57.7

// ---------------- scratch (device globals) ----------------
__device__ __half dA16 [N * M];   // KC*(x@y^T) fp16, row-major [i][j] (log2 units)
__device__ __half dAT16[N * M];   // transpose [j][i]
__device__ float  d_vt[N];        // potentials f32 (log2 units)
__device__ float  d_wt[M];
__device__ __half d_vth[N];       // fp16 copies
__device__ __half d_wth[M];
__device__ float  d_la[N];
__device__ float  d_lb[M];
__device__ float  d_x2[N];
__device__ float  d_y2[M];
__device__ float  d_an[N];
__device__ float  d_bn[M];
__device__ float  d_sums[2];

// ---------------- helpers ----------------
__device__ __forceinline__ float ex2(float x) {
    float r; asm("ex2.approx.f32 %0, %1;" : "=f"(r) : "f"(x)); return r;
}
__device__ __forceinline__ void fma2(ull& d, ull a, ull b) {
    asm("fma.rn.f32x2 %0, %1, %2, %0;" : "+l"(d) : "l"(a), "l"(b));
}
__device__ __forceinline__ ull bcast2(float a) {
    ull p; asm("mov.b64 %0, {%1, %1};" : "=l"(p) : "f"(a)); return p;
}
__device__ __forceinline__ void unpack2(ull p, float& lo, float& hi) {
    asm("mov.b64 {%0, %1}, %2;" : "=f"(lo), "=f"(hi) : "l"(p));
}
__device__ __forceinline__ ull pack2(float lo, float hi) {
    ull p; asm("mov.b64 %0, {%1, %2};" : "=l"(p) : "f"(lo), "f"(hi)); return p;
}

// ---------------- GEMM: 128x128 tile, 8x8/thread, emit fp16 A + AT ---------
__global__ void __launch_bounds__(256) gemm_kernel(const float* __restrict__ X,
                                                   const float* __restrict__ Y) {
    __shared__ __align__(16) char sbuf[34816];
    float*  sxT = (float*)sbuf;           // [32][132]
    float*  syT = sxT + 32 * 132;         // [32][132]
    __half* ts  = (__half*)sbuf;          // [128][136]

    int t  = threadIdx.x;
    int tx = t & 15, ty = t >> 4;
    int i0 = blockIdx.y * 128;
    int j0 = blockIdx.x * 128;

    ull acc[8][4];
    #pragma unroll
    for (int u = 0; u < 8; u++)
        #pragma unroll
        for (int v = 0; v < 4; v++) acc[u][v] = 0ull;

    #pragma unroll
    for (int k0 = 0; k0 < 64; k0 += 32) {
        if (k0) __syncthreads();
        #pragma unroll
        for (int it = 0; it < 4; it++) {
            int q = t + 256 * it;
            int r = q >> 3, c = q & 7;
            float4 fx = *reinterpret_cast<const float4*>(X + (size_t)(i0 + r) * D + k0 + c * 4);
            sxT[(c * 4 + 0) * 132 + r] = fx.x;
            sxT[(c * 4 + 1) * 132 + r] = fx.y;
            sxT[(c * 4 + 2) * 132 + r] = fx.z;
            sxT[(c * 4 + 3) * 132 + r] = fx.w;
            float4 fy = *reinterpret_cast<const float4*>(Y + (size_t)(j0 + r) * D + k0 + c * 4);
            syT[(c * 4 + 0) * 132 + r] = fy.x;
            syT[(c * 4 + 1) * 132 + r] = fy.y;
            syT[(c * 4 + 2) * 132 + r] = fy.z;
            syT[(c * 4 + 3) * 132 + r] = fy.w;
        }
        __syncthreads();

        #pragma unroll 8
        for (int k = 0; k < 32; k++) {
            float4 a0 = *reinterpret_cast<const float4*>(&sxT[k * 132 + ty * 8]);
            float4 a1 = *reinterpret_cast<const float4*>(&sxT[k * 132 + ty * 8 + 4]);
            float4 b0 = *reinterpret_cast<const float4*>(&syT[k * 132 + tx * 8]);
            float4 b1 = *reinterpret_cast<const float4*>(&syT[k * 132 + tx * 8 + 4]);
            ull bb0 = pack2(b0.x, b0.y), bb1 = pack2(b0.z, b0.w);
            ull bb2 = pack2(b1.x, b1.y), bb3 = pack2(b1.z, b1.w);
            float av[8] = {a0.x, a0.y, a0.z, a0.w, a1.x, a1.y, a1.z, a1.w};
            #pragma unroll
            for (int u = 0; u < 8; u++) {
                ull au = bcast2(av[u]);
                fma2(acc[u][0], au, bb0);
                fma2(acc[u][1], au, bb1);
                fma2(acc[u][2], au, bb2);
                fma2(acc[u][3], au, bb3);
            }
        }
    }

    __syncthreads();   // smem reads done; sbuf becomes ts

    #pragma unroll
    for (int u = 0; u < 8; u++) {
        float v[8];
        #pragma unroll
        for (int p = 0; p < 4; p++) {
            float lo, hi; unpack2(acc[u][p], lo, hi);
            v[2 * p] = lo * KC; v[2 * p + 1] = hi * KC;
        }
        uint4 o;
        ((__half2*)&o)[0] = __floats2half2_rn(v[0], v[1]);
        ((__half2*)&o)[1] = __floats2half2_rn(v[2], v[3]);
        ((__half2*)&o)[2] = __floats2half2_rn(v[4], v[5]);
        ((__half2*)&o)[3] = __floats2half2_rn(v[6], v[7]);
        *reinterpret_cast<uint4*>(dA16 + (size_t)(i0 + ty * 8 + u) * M + j0 + tx * 8) = o;
        const __half* oh = (const __half*)&o;
        #pragma unroll
        for (int e = 0; e < 8; e++)
            ts[(tx * 8 + e) * 136 + ty * 8 + u] = oh[e];
    }

    __syncthreads();
    #pragma unroll
    for (int it = 0; it < 8; it++) {
        int q = t + 256 * it;
        int jj = q >> 4, c = q & 15;
        uint4 o = *reinterpret_cast<const uint4*>(&ts[jj * 136 + c * 8]);
        *reinterpret_cast<uint4*>(dAT16 + (size_t)(j0 + jj) * N + i0 + c * 8) = o;
    }
}

// ---------------- row squared norms ----------------
__global__ void k_sqnorm(const float* __restrict__ X, const float* __restrict__ Y) {
    int w    = (blockIdx.x * blockDim.x + threadIdx.x) >> 5;
    int lane = threadIdx.x & 31;
    if (w >= N + M) return;
    const float* src = (w < N) ? (X + (size_t)w * D) : (Y + (size_t)(w - N) * D);
    float v0 = src[lane], v1 = src[lane + 32];
    float s = v0 * v0 + v1 * v1;
    #pragma unroll
    for (int off = 16; off; off >>= 1) s += __shfl_xor_sync(0xffffffffu, s, off);
    if (lane == 0) { if (w < N) d_x2[w] = s; else d_y2[w - N] = s; }
}

// ---------------- sums ----------------
__global__ void k_sum(const float* __restrict__ a, const float* __restrict__ b) {
    __shared__ float sa[1024], sb[1024];
    int t = threadIdx.x;
    float s1 = 0.f, s2 = 0.f;
    for (int i = t; i < N; i += 1024) s1 += a[i];
    for (int j = t; j < M; j += 1024) s2 += b[j];
    sa[t] = s1; sb[t] = s2; __syncthreads();
    for (int off = 512; off; off >>= 1) {
        if (t < off) { sa[t] += sa[t + off]; sb[t] += sb[t + off]; }
        __syncthreads();
    }
    if (t == 0) { d_sums[0] = sa[0]; d_sums[1] = sb[0]; }
}

// ---------------- init ----------------
__global__ void k_init(const float* __restrict__ a, const float* __restrict__ b) {
    int i = blockIdx.x * blockDim.x + threadIdx.x;
    if (i >= N) return;
    float lsa = logf(d_sums[0]), lsb = logf(d_sums[1]);
    float ai = a[i];
    d_la[i] = ALPHA * (logf(ai) - lsa);
    d_an[i] = ai / d_sums[0];
    float bi = b[i];
    float lb = ALPHA * (logf(bi) - lsb);
    d_lb[i] = lb;
    d_bn[i] = bi / d_sums[1];
    float w0 = lb - (ALPHA / EPS) * d_y2[i];
    d_wt[i]  = w0;
    d_wth[i] = __float2half_rn(w0);
}

// ---------------- LSE pass: warp/row, fp16 SIMD stream, f32 hot path -------
// lm estimated with HADD2/HMAX2 (fp16 A + fp16 w); when a chunk can matter
// (vote), the 8 terms are recomputed as f32: half2float(A) + w32 (errors only
// from A's fp16 rounding, which wash out in the LSE).
template <bool ROWPASS>
__global__ void __launch_bounds__(256) pass_kernel() {
    __shared__ __align__(16) __half sw16[8192];  // 16 KB, fp16 w
    __shared__ __align__(16) float  sw32[8192];  // 32 KB, f32 w
    const __half* __restrict__ Mat  = ROWPASS ? dA16  : dAT16;
    const __half* __restrict__ w16  = ROWPASS ? d_wth : d_vth;
    const float*  __restrict__ w32  = ROWPASS ? d_wt  : d_vt;
    const float*  __restrict__ lvec = ROWPASS ? d_la  : d_lb;
    float*  __restrict__ vout  = ROWPASS ? d_vt  : d_wt;
    __half* __restrict__ vouth = ROWPASS ? d_vth : d_wth;

    int t = threadIdx.x;
    {
        const uint4* s16 = reinterpret_cast<const uint4*>(w16);
        uint4* d16 = reinterpret_cast<uint4*>(sw16);
        #pragma unroll
        for (int it = 0; it < 4; it++) d16[t + 256 * it] = s16[t + 256 * it];
        const float4* s32 = reinterpret_cast<const float4*>(w32);
        float4* d32 = reinterpret_cast<float4*>(sw32);
        #pragma unroll
        for (int it = 0; it < 8; it++) d32[t + 256 * it] = s32[t + 256 * it];
    }
    __syncthreads();

    int warp = t >> 5, lane = t & 31;
    int row  = blockIdx.x * 8 + warp;
    const uint4* rp  = reinterpret_cast<const uint4*>(Mat + (size_t)row * M); // 8 halves
    const uint4* swv = reinterpret_cast<const uint4*>(sw16);

    float m = -INFINITY, s = 0.f;

    #pragma unroll 8
    for (int c = 0; c < 32; c++) {
        int idx = c * 32 + lane;
        uint4 av = rp[idx];
        uint4 wv = swv[idx];
        const __half2* ah = (const __half2*)&av;
        const __half2* wh = (const __half2*)&wv;
        __half2 t0 = __hadd2(ah[0], wh[0]);
        __half2 t1 = __hadd2(ah[1], wh[1]);
        __half2 t2 = __hadd2(ah[2], wh[2]);
        __half2 t3 = __hadd2(ah[3], wh[3]);
        __half2 mm = __hmax2(__hmax2(t0, t1), __hmax2(t2, t3));
        float lmf = fmaxf(__low2float(mm), __high2float(mm));
        // skipped chunks contribute < 2^-35 of the max (margin covers fp16 err)
        if (!__all_sync(0xffffffffu, lmf < m - 40.f)) {
            float nm = fmaxf(m, lmf);
            float r  = ex2(m - nm);
            int e = idx * 8;
            float4 wA = *reinterpret_cast<const float4*>(&sw32[e]);
            float4 wB = *reinterpret_cast<const float4*>(&sw32[e + 4]);
            float2 f0 = __half22float2(ah[0]);
            float2 f1 = __half22float2(ah[1]);
            float2 f2 = __half22float2(ah[2]);
            float2 f3 = __half22float2(ah[3]);
            float e8 = ((ex2(f0.x + wA.x - nm) + ex2(f0.y + wA.y - nm))
                      + (ex2(f1.x + wA.z - nm) + ex2(f1.y + wA.w - nm)))
                     + ((ex2(f2.x + wB.x - nm) + ex2(f2.y + wB.y - nm))
                      + (ex2(f3.x + wB.z - nm) + ex2(f3.y + wB.w - nm)));
            s = fmaf(s, r, e8);
            m = nm;
        }
    }

    #pragma unroll
    for (int off = 16; off; off >>= 1) {
        float m2 = __shfl_xor_sync(0xffffffffu, m, off);
        float s2 = __shfl_xor_sync(0xffffffffu, s, off);
        float nm = fmaxf(m, m2);
        s = s * ex2(m - nm) + s2 * ex2(m2 - nm);
        m = nm;
    }
    if (lane == 0) {
        float r = lvec[row] - (m + log2f(s));
        vout[row]  = r;
        vouth[row] = __float2half_rn(r);
    }
}

// ---------------- final reduction ----------------
__global__ void k_final(float* __restrict__ out) {
    __shared__ float sm[1024];
    int t = threadIdx.x;
    float s = 0.f;
    for (int i = t; i < N; i += 1024)
        s += d_an[i] * (d_x2[i] + EPS * LN2 * (d_vt[i] - d_la[i]));
    for (int j = t; j < M; j += 1024)
        s += d_bn[j] * (d_y2[j] + EPS * LN2 * (d_wt[j] - d_lb[j]));
    sm[t] = s; __syncthreads();
    for (int off = 512; off; off >>= 1) {
        if (t < off) sm[t] += sm[t + off];
        __syncthreads();
    }
    if (t == 0) out[0] = sm[0];
}

// ---------------- launch ----------------
// gemm launched FIRST (depends only on x,y) so the ncu capture window
// (-s 5 -c 1 -> 6th launch) lands on a pass kernel for diagnosis.
extern "C" void kernel_launch(void* const* d_in, const int* in_sizes, int n_in,
                              void* d_out, int out_size) {
    const float* a = (const float*)d_in[0];
    const float* x = (const float*)d_in[1];
    const float* b = (const float*)d_in[2];
    const float* y = (const float*)d_in[3];
    float* out = (float*)d_out;

    gemm_kernel<<<dim3(M / 128, N / 128), 256>>>(x, y);   // launch 1
    k_sqnorm<<<(N + M) / 8, 256>>>(x, y);                 // launch 2
    k_sum<<<1, 1024>>>(a, b);                             // launch 3
    k_init<<<N / 256, 256>>>(a, b);                       // launch 4

    for (int it = 0; it < NIT; ++it) {
        pass_kernel<true ><<<N / 8, 256>>>();  // launch 5, 7, 9, ...
        pass_kernel<false><<<M / 8, 256>>>();  // launch 6 <- ncu capture
    }
    pass_kernel<true><<<N / 8, 256>>>();       // f_fin; g_fin == g_20
    k_final<<<1, 1024>>>(out);
}